// round 5
// baseline (speedup 1.0000x reference)
#include <cuda_runtime.h>

// Census loss, pair-symmetric, 2x2 pixels/thread, row-streaming windows.
// total = sum_{unordered pairs (a,b), off in H(24)} t * (v(a)+v(b))
// t = 1 - 0.1*rcp(0.1+e^2), e = cx-cy, c = d*rsqrt(7.29+d^2), d = 3*(g(b)-g(a)).
// Output = total / (49*8*256*256).

#define IMG   256
#define IMG2  65536
#define SWP   40      // padded shared row pitch (floats), 38 used
#define SROWS 38      // 32 + 6 halo
#define NPX   1444    // 38*38

__device__ __forceinline__ float frsqrt_a(float x){ float r; asm("rsqrt.approx.f32 %0, %1;" : "=f"(r) : "f"(x)); return r; }
__device__ __forceinline__ float frcp_a  (float x){ float r; asm("rcp.approx.f32 %0, %1;"   : "=f"(r) : "f"(x)); return r; }

// rc = 1/(0.1+e^2); e = dX*rsq(dX)-dY*rsq(dY)   (11 issue slots incl. acc)
__device__ __forceinline__ float pair_rc(float nbx, float nby, float cenx, float ceny)
{
    float dX = nbx - cenx;
    float dY = nby - ceny;
    float rX = frsqrt_a(fmaf(dX, dX, 7.29f));
    float rY = frsqrt_a(fmaf(dY, dY, 7.29f));
    float cy = dY * rY;
    float e  = fmaf(dX, rX, -cy);
    return frcp_a(fmaf(e, e, 0.1f));
}

template<bool BORDER>
__device__ __forceinline__ float census4(const float2* __restrict__ rx2,
                                         const float2* __restrict__ ry2,
                                         int R, int C)
{
    float vq[5], vcol[8], va00, va01, va10, va11;
    if (BORDER) {
#pragma unroll
        for (int q = 0; q < 5; q++) vq[q]   = ((unsigned)(R + q - 3) < 250u) ? 1.f : 0.f;
#pragma unroll
        for (int j = 0; j < 8; j++) vcol[j] = ((unsigned)(C + j - 6) < 250u) ? 1.f : 0.f;
        va00 = vq[0] * vcol[3];  va01 = vq[0] * vcol[4];
        va10 = vq[1] * vcol[3];  va11 = vq[1] * vcol[4];
    }

    float cenx[2][2], ceny[2][2];
    float accr = 0.f, accw = 0.f;

#pragma unroll
    for (int dq = 0; dq < 5; dq++) {
        // load window row dq: 8 floats per image (4 aligned LDS.64)
        float wx[8], wy[8];
        {
            const float2* px = rx2 + dq * (SWP / 2);
            const float2* py = ry2 + dq * (SWP / 2);
#pragma unroll
            for (int k = 0; k < 4; k++) {
                float2 vx = px[k], vy = py[k];
                wx[2 * k] = vx.x;  wx[2 * k + 1] = vx.y;
                wy[2 * k] = vy.x;  wy[2 * k + 1] = vy.y;
            }
        }
        if (dq == 0) { cenx[0][0] = wx[3]; cenx[0][1] = wx[4]; ceny[0][0] = wy[3]; ceny[0][1] = wy[4]; }
        if (dq == 1) { cenx[1][0] = wx[3]; cenx[1][1] = wx[4]; ceny[1][0] = wy[3]; ceny[1][1] = wy[4]; }

#pragma unroll
        for (int cr = 0; cr < 2; cr++) {
            const int dy = dq - cr;
            if (dy < 0 || dy > 3) continue;
#pragma unroll
            for (int ci = 0; ci < 2; ci++) {
                const float cax = cenx[cr][ci], cay = ceny[cr][ci];
                const float vaa = BORDER ? (cr ? (ci ? va11 : va10) : (ci ? va01 : va00)) : 0.f;
                if (dy == 0) {
#pragma unroll
                    for (int dx = 1; dx <= 3; dx++) {
                        const int j = 3 + ci + dx;
                        float rc = pair_rc(wx[j], wy[j], cax, cay);
                        if (BORDER) {
                            float w = fmaf(vq[dq], vcol[j], vaa);
                            accw += w; accr = fmaf(w, rc, accr);
                        } else accr += rc;
                    }
                } else {
#pragma unroll
                    for (int dx = -3; dx <= 3; dx++) {
                        const int j = ci + dx + 3;
                        float rc = pair_rc(wx[j], wy[j], cax, cay);
                        if (BORDER) {
                            float w = fmaf(vq[dq], vcol[j], vaa);
                            accw += w; accr = fmaf(w, rc, accr);
                        } else accr += rc;
                    }
                }
            }
        }
    }
    // interior: 96 pairs, weight 2: sum = 2*(96 - 0.1*accr)
    return BORDER ? fmaf(-0.1f, accr, accw) : fmaf(-0.2f, accr, 192.f);
}

__global__ __launch_bounds__(256, 4)
void census_loss_kernel(const float* __restrict__ x,
                        const float* __restrict__ y,
                        float* __restrict__ out)
{
    __shared__ __align__(8) float sgx[SROWS * SWP];
    __shared__ __align__(8) float sgy[SROWS * SWP];

    const int b    = blockIdx.z;
    const int row0 = blockIdx.y * 32;
    const int col0 = blockIdx.x * 32;
    const int tid  = threadIdx.y * 16 + threadIdx.x;

    const float* xb = x + (size_t)b * 3 * IMG2;
    const float* yb = y + (size_t)b * 3 * IMG2;

    const bool interior = (blockIdx.x - 1u < 6u) & (blockIdx.y - 1u < 6u);

    // 3*grayscale tile + halo
    if (interior) {
        const int base = (row0 - 3) * IMG + (col0 - 3);
#pragma unroll
        for (int it = 0; it < 6; it++) {
            int i = tid + it * 256;
            if (it == 5 && i >= NPX) break;
            int lr = i / 38;
            int lc = i - lr * 38;
            int o  = base + lr * IMG + lc;
            sgx[lr * SWP + lc] = xb[o] + xb[o + IMG2] + xb[o + 2 * IMG2];
            sgy[lr * SWP + lc] = yb[o] + yb[o + IMG2] + yb[o + 2 * IMG2];
        }
    } else {
        for (int i = tid; i < NPX; i += 256) {
            int lr = i / 38;
            int lc = i - lr * 38;
            int gr = row0 - 3 + lr;
            int gc = col0 - 3 + lc;
            float gx = 0.f, gy = 0.f;
            if ((unsigned)gr < 256u && (unsigned)gc < 256u) {
                int o = gr * IMG + gc;
                gx = xb[o] + xb[o + IMG2] + xb[o + 2 * IMG2];
                gy = yb[o] + yb[o + IMG2] + yb[o + 2 * IMG2];
            }
            sgx[lr * SWP + lc] = gx;
            sgy[lr * SWP + lc] = gy;
        }
    }
    __syncthreads();

    const int tx = threadIdx.x;     // 0..15 -> pixel cols 2tx, 2tx+1
    const int ty = threadIdx.y;     // 0..15 -> pixel rows 2ty, 2ty+1

    // float2 window base: padded row 2ty+3 (=center row), float col 2tx
    // covers tile-local cols 2tx-3 .. 2tx+4
    const float2* rx2 = (const float2*)sgx + (2 * ty + 3) * (SWP / 2) + tx;
    const float2* ry2 = (const float2*)sgy + (2 * ty + 3) * (SWP / 2) + tx;

    const int R = row0 + 2 * ty;
    const int C = col0 + 2 * tx;

    float res = interior ? census4<false>(rx2, ry2, R, C)
                         : census4<true >(rx2, ry2, R, C);

    // warp + block reduction (8 warps)
#pragma unroll
    for (int s = 16; s > 0; s >>= 1)
        res += __shfl_xor_sync(0xFFFFFFFFu, res, s);

    __shared__ float wsum[8];
    if ((tid & 31) == 0) wsum[tid >> 5] = res;
    __syncthreads();
    if (tid < 8) {
        float v = wsum[tid];
        v += __shfl_xor_sync(0xFFu, v, 4);
        v += __shfl_xor_sync(0xFFu, v, 2);
        v += __shfl_xor_sync(0xFFu, v, 1);
        if (tid == 0)
            atomicAdd(out, v * (1.f / 25690112.f));   // 1/(49*8*256*256)
    }
}

extern "C" void kernel_launch(void* const* d_in, const int* in_sizes, int n_in,
                              void* d_out, int out_size)
{
    const float* x = (const float*)d_in[0];
    const float* y = (const float*)d_in[1];
    float* out = (float*)d_out;

    cudaMemsetAsync(out, 0, sizeof(float));

    dim3 block(16, 16, 1);
    dim3 grid(8, 8, 8);   // 512 blocks
    census_loss_kernel<<<grid, block>>>(x, y, out);
}

// round 6
// speedup vs baseline: 1.2712x; 1.2712x over previous
#include <cuda_runtime.h>

// Census loss, pair-symmetric, f32x2-packed (2 horizontally-adjacent pixels/thread).
// total = sum_{a} sum_{off in H(24)} t(a,off) * (v(a)+v(a+off))
// t = 1 - 0.1*rc,  rc = 1/(0.1+e^2),  e = cx-cy,  c = d*rsqrt(7.29+d^2),
// d = g3(b)-g3(a), g3 = r+g+b (unnormalized grayscale *3 folded into 7.29).
// Interior blocks: all weights == 2  ->  res = 2*(48 - 0.1*sum(rc)) per thread.

#define IMG   256
#define IMG2  65536
#define TCOLS 32
#define TROWS 16
#define SW    38   // TCOLS + 6
#define SWR   22   // TROWS + 6
#define SW2   19   // SW/2 in float2

typedef unsigned long long ull;

__device__ __forceinline__ float frsqrt_a(float x){ float r; asm("rsqrt.approx.f32 %0, %1;" : "=f"(r) : "f"(x)); return r; }
__device__ __forceinline__ float frcp_a  (float x){ float r; asm("rcp.approx.f32 %0, %1;"   : "=f"(r) : "f"(x)); return r; }

__device__ __forceinline__ ull pk(float lo, float hi){ ull r; asm("mov.b64 %0, {%1, %2};" : "=l"(r) : "f"(lo), "f"(hi)); return r; }
__device__ __forceinline__ float2 upk(ull v){ float2 f; asm("mov.b64 {%0, %1}, %2;" : "=f"(f.x), "=f"(f.y) : "l"(v)); return f; }
__device__ __forceinline__ ull fma2(ull a, ull b, ull c){ ull r; asm("fma.rn.f32x2 %0, %1, %2, %3;" : "=l"(r) : "l"(a), "l"(b), "l"(c)); return r; }
__device__ __forceinline__ ull mul2(ull a, ull b){ ull r; asm("mul.rn.f32x2 %0, %1, %2;" : "=l"(r) : "l"(a), "l"(b)); return r; }

// packed rc = 1/(0.1+e^2) for two pixel-pairs at once
__device__ __forceinline__ float2 pair_rc2(ull nbx, ull nby, ull cenx, ull ceny,
                                           ull NEG1, ull C729, ull C01)
{
    ull dX = fma2(cenx, NEG1, nbx);          // nb - cen
    ull dY = fma2(ceny, NEG1, nby);
    ull aX = fma2(dX, dX, C729);
    ull aY = fma2(dY, dY, C729);
    float2 a = upk(aX);
    ull rX = pk(frsqrt_a(a.x), frsqrt_a(a.y));
    float2 b = upk(aY);
    ull rY = pk(frsqrt_a(b.x), frsqrt_a(b.y));
    ull cx = mul2(dX, rX);
    ull cy = mul2(dY, rY);
    ull e  = fma2(cy, NEG1, cx);             // cx - cy
    ull dn = fma2(e, e, C01);
    float2 d = upk(dn);
    float2 rc;
    rc.x = frcp_a(d.x);
    rc.y = frcp_a(d.y);
    return rc;
}

template<bool BORDER>
__device__ __forceinline__ float census_body(const float2* __restrict__ px0,
                                             const float2* __restrict__ py0,
                                             int r, int c0)
{
    const ull NEG1 = pk(-1.f, -1.f);
    const ull C729 = pk(7.29f, 7.29f);
    const ull C01  = pk(0.1f, 0.1f);

    float vrow[4], vcw[8];
    float va0 = 0.f, va1 = 0.f;
    if (BORDER) {
#pragma unroll
        for (int d = 0; d < 4; d++) vrow[d] = ((unsigned)(r + d - 3) < 250u) ? 1.f : 0.f;
#pragma unroll
        for (int j = 0; j < 8; j++) vcw[j] = ((unsigned)(c0 - 6 + j) < 250u) ? 1.f : 0.f;
        va0 = vrow[0] * vcw[3];
        va1 = vrow[0] * vcw[4];
    }

    float accA = 0.f, accB = 0.f;   // two chains for ILP (interior: sum rc)
    float accw = 0.f;               // border: sum of weights

    // center row (dy = 0): window cols 2..7 (float2 elems 1..3)
    float2 x1 = px0[1], x2 = px0[2], x3 = px0[3];
    float2 y1 = py0[1], y2 = py0[2], y3 = py0[3];
    const ull cenx = pk(x1.y, x2.x);
    const ull ceny = pk(y1.y, y2.x);

#pragma unroll
    for (int dx = 1; dx <= 3; dx++) {
        float n0x = (dx == 1) ? x2.x : (dx == 2) ? x2.y : x3.x;
        float n1x = (dx == 1) ? x2.y : (dx == 2) ? x3.x : x3.y;
        float n0y = (dx == 1) ? y2.x : (dx == 2) ? y2.y : y3.x;
        float n1y = (dx == 1) ? y2.y : (dx == 2) ? y3.x : y3.y;
        float2 rc = pair_rc2(pk(n0x, n1x), pk(n0y, n1y), cenx, ceny, NEG1, C729, C01);
        if (BORDER) {
            float w0 = fmaf(vrow[0], vcw[dx + 3], va0);
            float w1 = fmaf(vrow[0], vcw[dx + 4], va1);
            accw += w0 + w1;
            accA = fmaf(w0, rc.x, accA);
            accB = fmaf(w1, rc.y, accB);
        } else {
            accA += rc.x;
            accB += rc.y;
        }
    }

#pragma unroll
    for (int dy = 1; dy < 4; dy++) {
        const float2* prx = px0 + dy * SW2;
        const float2* pry = py0 + dy * SW2;
        float2 a0 = prx[0], a1 = prx[1], a2 = prx[2], a3 = prx[3];
        float2 b0 = pry[0], b1 = pry[1], b2 = pry[2], b3 = pry[3];
        float vx[8] = {a0.x, a0.y, a1.x, a1.y, a2.x, a2.y, a3.x, a3.y};
        float vy[8] = {b0.x, b0.y, b1.x, b1.y, b2.x, b2.y, b3.x, b3.y};
#pragma unroll
        for (int j = 0; j < 7; j++) {
            float2 rc = pair_rc2(pk(vx[j], vx[j + 1]), pk(vy[j], vy[j + 1]),
                                 cenx, ceny, NEG1, C729, C01);
            if (BORDER) {
                float w0 = fmaf(vrow[dy], vcw[j], va0);
                float w1 = fmaf(vrow[dy], vcw[j + 1], va1);
                accw += w0 + w1;
                accA = fmaf(w0, rc.x, accA);
                accB = fmaf(w1, rc.y, accB);
            } else {
                accA += rc.x;
                accB += rc.y;
            }
        }
    }

    float s = accA + accB;
    // interior: 48 pairs, weight 2 each: 2*(48 - 0.1*sum_rc)
    return BORDER ? fmaf(-0.1f, s, accw) : fmaf(-0.2f, s, 96.f);
}

__global__ __launch_bounds__(256, 3)
void census_loss_kernel(const float* __restrict__ x,
                        const float* __restrict__ y,
                        float* __restrict__ out)
{
    __shared__ __align__(16) float sgx[SWR * SW];
    __shared__ __align__(16) float sgy[SWR * SW];

    const int b    = blockIdx.z;
    const int row0 = blockIdx.y * TROWS;
    const int col0 = blockIdx.x * TCOLS;
    const int tid  = threadIdx.y * 16 + threadIdx.x;

    const float* xb = x + (size_t)b * 3 * IMG2;
    const float* yb = y + (size_t)b * 3 * IMG2;

    // 3*grayscale tile + halo (zero outside image; weight 0 kills those pairs)
    for (int i = tid; i < SWR * SW; i += 256) {
        int lr = i / SW;
        int lc = i - lr * SW;
        int gr = row0 - 3 + lr;
        int gc = col0 - 3 + lc;
        float gx = 0.f, gy = 0.f;
        if ((unsigned)gr < 256u && (unsigned)gc < 256u) {
            int o = gr * IMG + gc;
            gx = xb[o] + xb[o + IMG2] + xb[o + 2 * IMG2];
            gy = yb[o] + yb[o + IMG2] + yb[o + 2 * IMG2];
        }
        sgx[i] = gx;
        sgy[i] = gy;
    }
    __syncthreads();

    const int tx = threadIdx.x;          // 0..15
    const int ty = threadIdx.y;          // 0..15
    const int baseoff = (ty + 3) * SW + 2 * tx;   // even -> 8B aligned
    const float2* px0 = (const float2*)(sgx + baseoff);
    const float2* py0 = (const float2*)(sgy + baseoff);

    const int r  = row0 + ty;
    const int c0 = col0 + 2 * tx;

    const bool interior = (blockIdx.x - 1u < 6u) & (blockIdx.y - 1u < 14u);

    float acc = interior ? census_body<false>(px0, py0, r, c0)
                         : census_body<true >(px0, py0, r, c0);

    // warp + block reduction
#pragma unroll
    for (int s = 16; s > 0; s >>= 1)
        acc += __shfl_xor_sync(0xFFFFFFFFu, acc, s);

    __shared__ float wsum[8];
    if ((tid & 31) == 0) wsum[tid >> 5] = acc;
    __syncthreads();
    if (tid < 8) {
        float v = wsum[tid];
        v += __shfl_xor_sync(0xFFu, v, 4);
        v += __shfl_xor_sync(0xFFu, v, 2);
        v += __shfl_xor_sync(0xFFu, v, 1);
        if (tid == 0)
            atomicAdd(out, v * (1.f / 25690112.f));   // 1/(49*8*256*256)
    }
}

extern "C" void kernel_launch(void* const* d_in, const int* in_sizes, int n_in,
                              void* d_out, int out_size)
{
    const float* x = (const float*)d_in[0];
    const float* y = (const float*)d_in[1];
    float* out = (float*)d_out;

    cudaMemsetAsync(out, 0, sizeof(float));

    dim3 block(16, 16, 1);
    dim3 grid(IMG / TCOLS, IMG / TROWS, 8);   // 8 x 16 x 8 = 1024 blocks
    census_loss_kernel<<<grid, block>>>(x, y, out);
}